// round 14
// baseline (speedup 1.0000x reference)
#include <cuda_runtime.h>

// ---------------------------------------------------------------------------
// EDeeperGCN edge classifier, factorized:
//   A = x @ W1[:128] + b1   (per node)      k1 (quarter-tile CTAs)
//   B = x @ W1[128:]        (per node)      k1
//   out[e] = relu(A[src[e]] + B[dst[e]]) @ W2 + b2        k2
//
// R9: 122.9us. k1 31.1us with issue 30.7%, fma 27.8% -> LDS-latency bound at
// 4 warps/SMSP. This round: k1 quarter-tiles (Ws 64 cols, smem 73KB, 3
// CTAs/SM = 6 warps/SMSP, grid 500); k2 phase-A gather batch 4 -> 8 edges
// (MLP 16/warp).
// ---------------------------------------------------------------------------

#define HID 128
#define NOUT 10
#define MAX_NODES 10016
#define K1_ROWS 80
#define XP 82               // transposed Xs pitch (floats): 80 + 2 (even->8B ok)
#define K2_TILE 128
#define HP 66               // per-pass H pitch (floats): 64 + 2 pad

__device__ float g_A[MAX_NODES * HID];
__device__ float g_B[MAX_NODES * HID];
__device__ int g_idx64;

// --------------------------------------------------------------------------
// detect int64 vs int32 edge_index storage. 64 parallel strided samples;
// any u64 word >= 2^32 proves int32 packing (node ids < 10000 < 2^32).
// --------------------------------------------------------------------------
__global__ void detect_kernel(const unsigned long long* __restrict__ p,
                              int n_edges) {
    int tid = threadIdx.x;              // 64 threads
    long stride = n_edges > 64 ? n_edges / 64 : 1;
    int big = 0;
    long w = (long)tid * stride;
    if (w < n_edges) big = (p[w] >= (1ULL << 32));
    int any32 = __syncthreads_or(big);
    if (tid == 0) g_idx64 = any32 ? 0 : 1;
}

// --------------------------------------------------------------------------
// k1: quarter-GEMM per CTA. Grid = 4*nblk; group g = blockIdx.x / nblk:
//   half = g>>1 (0 -> A / W1 rows 0..127 (+b1), 1 -> B / W1 rows 128..255)
//   q    = g&1  (output cols q*64 .. q*64+63)
// 256 threads; Ws [128][64] = 32 KB, Xs transposed [128][XP] = 41 KB ->
// 73 KB smem, 3 CTAs/SM (24 warps/SM, 6/SMSP for LDS-latency cover).
// Thread (tx,ty): cols tx+32j (j<2), rows ty*10..+9 as 5 f32x2 pairs.
// Inner loop per k: 5 LDS.64 (broadcast row pairs) + 2 LDS.32 (W) + 2 dup
// + 10 fma.rn.f32x2 = 19 instr.
// --------------------------------------------------------------------------
__global__ void __launch_bounds__(256, 3)
k1_kernel(const float* __restrict__ x, const float* __restrict__ W1,
          const float* __restrict__ b1, int n_nodes, int nblk) {
    extern __shared__ float sm[];
    float* Ws = sm;                 // [128][64]   Ws[k][c]
    float* Xs = sm + 128 * 64;      // [128][XP]   Xs[k][r]  (transposed)
    const int tid = threadIdx.x;

    const int g    = blockIdx.x / nblk;      // 0..3
    const int blk  = blockIdx.x - g * nblk;
    const int half = g >> 1;                 // 0=A, 1=B
    const int c0   = (g & 1) << 6;           // col offset 0 or 64

    // stage W quarter: Ws[k][c] = W1[(k + half*128)*128 + c0 + c], float4
    const float* Wsrc = W1 + half * 128 * 128 + c0;
    for (int v = tid; v < 2048; v += 256) {
        int k  = v >> 4;
        int c4 = (v & 15) << 2;
        *(float4*)(Ws + (k << 6) + c4) = *(const float4*)(Wsrc + (k << 7) + c4);
    }

    // stage x tile transposed: Xs[k][r] = x[rows0+r][k]
    const int rows0 = blk * K1_ROWS;
    for (int idx = tid; idx < K1_ROWS * 128; idx += 256) {
        int r = idx >> 7;
        int k = idx & 127;
        float v = 0.f;
        if (rows0 + r < n_nodes) v = x[(long)(rows0 + r) * 128 + k];
        Xs[k * XP + r] = v;
    }
    __syncthreads();

    const int tx = tid & 31;        // col lane: cols c0 + tx + 32*j
    const int ty = tid >> 5;        // row group: rows ty*10 .. ty*10+9
    const int rbase = ty * 10;

    unsigned long long acc[5][2];
    #pragma unroll
    for (int j = 0; j < 2; j++) {
        unsigned long long init = 0ULL;
        if (half == 0) {
            unsigned u = __float_as_uint(__ldg(b1 + c0 + tx + 32 * j));
            asm("mov.b64 %0, {%1, %1};" : "=l"(init) : "r"(u));
        }
        #pragma unroll
        for (int p = 0; p < 5; p++) acc[p][j] = init;
    }

    #pragma unroll 4
    for (int k = 0; k < 128; k++) {
        unsigned long long xp[5];
        const float* xk = Xs + k * XP + rbase;
        #pragma unroll
        for (int p = 0; p < 5; p++)
            xp[p] = *(const unsigned long long*)(xk + 2 * p);   // LDS.64 pair
        #pragma unroll
        for (int j = 0; j < 2; j++) {
            unsigned wu = __float_as_uint(Ws[(k << 6) + tx + (j << 5)]);
            unsigned long long wd;
            asm("mov.b64 %0, {%1, %1};" : "=l"(wd) : "r"(wu));
            #pragma unroll
            for (int p = 0; p < 5; p++)
                asm("fma.rn.f32x2 %0, %1, %2, %0;"
                    : "+l"(acc[p][j]) : "l"(xp[p]), "l"(wd));
        }
    }

    float* dst = half ? g_B : g_A;
    #pragma unroll
    for (int p = 0; p < 5; p++) {
        int g0 = rows0 + rbase + 2 * p;
        #pragma unroll
        for (int j = 0; j < 2; j++) {
            unsigned lo, hi;
            asm("mov.b64 {%0, %1}, %2;" : "=r"(lo), "=r"(hi) : "l"(acc[p][j]));
            int c = c0 + tx + (j << 5);
            if (g0 < n_nodes)     dst[(long)g0 * 128 + c]       = __uint_as_float(lo);
            if (g0 + 1 < n_nodes) dst[(long)(g0 + 1) * 128 + c] = __uint_as_float(hi);
        }
    }
}

// --------------------------------------------------------------------------
// k2: per-edge  h = relu(A[src]+B[dst]);  out = h @ W2 + b2
// 128 threads / 128-edge tile, TWO feature passes of 64 (smem ~40KB, 5
// CTAs/SM, 20 warps/SM). Phase A batches 8 edges (16 LDG.64 in flight).
// --------------------------------------------------------------------------
__global__ void __launch_bounds__(128, 5)
k2_kernel(const void* __restrict__ eidx, const float* __restrict__ W2,
          const float* __restrict__ b2, float* __restrict__ out, int n_edges) {
    extern __shared__ float sm[];
    float* Hs = sm;                                      // [128][HP]
    unsigned long long* W2p =
        (unsigned long long*)(sm + K2_TILE * HP);        // [5][128] u64 pairs
    int* sidx = (int*)(W2p + 5 * 128);
    int* didx = sidx + K2_TILE;
    const int tid = threadIdx.x;

    for (int i = tid; i < 5 * 128; i += 128) {
        int p = i >> 7, j = i & 127;
        unsigned u0 = __float_as_uint(W2[j * 10 + 2 * p]);
        unsigned u1 = __float_as_uint(W2[j * 10 + 2 * p + 1]);
        unsigned long long w;
        asm("mov.b64 %0, {%1, %2};" : "=l"(w) : "r"(u0), "r"(u1));
        W2p[i] = w;
    }

    const int e0 = blockIdx.x << 7;
    {
        int e = e0 + tid;
        int s = 0, d = 0;
        if (e < n_edges) {
            if (g_idx64) {
                const long long* p = (const long long*)eidx;
                s = (int)p[e]; d = (int)p[n_edges + e];
            } else {
                const int* p = (const int*)eidx;
                s = p[e]; d = p[n_edges + e];
            }
        }
        sidx[tid] = s; didx[tid] = d;
    }
    __syncthreads();

    unsigned long long acc[5];
    #pragma unroll
    for (int p = 0; p < 5; p++) {
        unsigned u0 = __float_as_uint(__ldg(b2 + 2 * p));
        unsigned u1 = __float_as_uint(__ldg(b2 + 2 * p + 1));
        asm("mov.b64 %0, {%1, %2};" : "=l"(acc[p]) : "r"(u0), "r"(u1));
    }

    const int w = tid >> 5, l = tid & 31;
    const ulonglong2* W2v = (const ulonglong2*)W2p;   // [5][64] (j,j+1) pairs

    #pragma unroll
    for (int pass = 0; pass < 2; pass++) {
        const int fbase = pass << 6;

        // phase A: gather + relu, 8-edge batches (MLP=16 LDG.64 per warp)
        #pragma unroll
        for (int eo = 0; eo < 32; eo += 8) {
            float2 av[8], bv[8];
            #pragma unroll
            for (int u = 0; u < 8; u++) {
                int el = (w << 5) + eo + u;
                int s = sidx[el], d = didx[el];
                av[u] = *(const float2*)(g_A + ((long)s << 7) + fbase + (l << 1));
                bv[u] = *(const float2*)(g_B + ((long)d << 7) + fbase + (l << 1));
            }
            #pragma unroll
            for (int u = 0; u < 8; u++) {
                int el = (w << 5) + eo + u;
                float2 h;
                h.x = fmaxf(av[u].x + bv[u].x, 0.f);
                h.y = fmaxf(av[u].y + bv[u].y, 0.f);
                *(float2*)(Hs + el * HP + (l << 1)) = h;
            }
        }
        __syncthreads();

        const float* hrow = Hs + tid * HP;
        const int jp0 = pass << 5;
        #pragma unroll 8
        for (int t = 0; t < 32; t++) {
            float2 h2 = *(const float2*)(hrow + (t << 1));
            unsigned long long hh0, hh1;
            asm("mov.b64 %0, {%1, %1};" : "=l"(hh0) : "r"(__float_as_uint(h2.x)));
            asm("mov.b64 %0, {%1, %1};" : "=l"(hh1) : "r"(__float_as_uint(h2.y)));
            #pragma unroll
            for (int p = 0; p < 5; p++) {
                ulonglong2 wv = W2v[(p << 6) + jp0 + t];
                asm("fma.rn.f32x2 %0, %1, %2, %0;" : "+l"(acc[p]) : "l"(hh0), "l"(wv.x));
                asm("fma.rn.f32x2 %0, %1, %2, %0;" : "+l"(acc[p]) : "l"(hh1), "l"(wv.y));
            }
        }
        if (pass == 0) __syncthreads();
    }

    int e = e0 + tid;
    if (e < n_edges) {
        float* op = out + (long)e * 10;
        #pragma unroll
        for (int p = 0; p < 5; p++)
            *(unsigned long long*)(op + 2 * p) = acc[p];
    }
}

// --------------------------------------------------------------------------
extern "C" void kernel_launch(void* const* d_in, const int* in_sizes, int n_in,
                              void* d_out, int out_size) {
    const float* x  = (const float*)d_in[0];
    const void* eix = d_in[1];
    const float* W1 = (const float*)d_in[2];
    const float* b1 = (const float*)d_in[3];
    const float* W2 = (const float*)d_in[4];
    const float* b2 = (const float*)d_in[5];
    float* out = (float*)d_out;

    int n_nodes = in_sizes[0] / HID;
    int n_edges = in_sizes[1] / 2;
    int nblk = (n_nodes + K1_ROWS - 1) / K1_ROWS;        // 125

    const int K1_SMEM = (128 * 64 + 128 * XP) * 4;                    // ~73 KB
    const int K2_SMEM = K2_TILE * HP * 4 + 5 * 128 * 8 + K2_TILE * 8; // ~40 KB

    cudaFuncSetAttribute(k1_kernel, cudaFuncAttributeMaxDynamicSharedMemorySize, K1_SMEM);
    cudaFuncSetAttribute(k2_kernel, cudaFuncAttributeMaxDynamicSharedMemorySize, K2_SMEM);

    k1_kernel<<<4 * nblk, 256, K1_SMEM>>>(x, W1, b1, n_nodes, nblk);
    detect_kernel<<<1, 64>>>((const unsigned long long*)eix, n_edges);
    k2_kernel<<<(n_edges + K2_TILE - 1) / K2_TILE, K2_TILE, K2_SMEM>>>(eix, W2, b2, out, n_edges);
}